// round 1
// baseline (speedup 1.0000x reference)
#include <cuda_runtime.h>
#include <cstdint>

// Problem constants (match reference)
#define NLVL   16
#define LOG_T  19
#define TSIZE  (1u << LOG_T)          // 524288
#define TMASK  (TSIZE - 1u)
#define P2     2654435761u
#define P3     805459861u

// 64 MB repacked table: [L, T] of float2 (feature-interleaved)
__device__ float2 g_packed[NLVL * TSIZE];

// ---------------------------------------------------------------------------
// Kernel 1: repack hashmap [L, F, T] -> [L, T, {f0,f1}]
// Fully coalesced reads and writes; ~128 MB of streamed traffic.
// ---------------------------------------------------------------------------
__global__ void repack_kernel(const float* __restrict__ hm) {
    const int total = NLVL * (int)TSIZE;
    for (int i = blockIdx.x * blockDim.x + threadIdx.x; i < total;
         i += gridDim.x * blockDim.x) {
        const int l = i >> LOG_T;
        const int t = i & (int)TMASK;
        const float* base = hm + (size_t)l * 2u * TSIZE;
        g_packed[i] = make_float2(__ldg(base + t), __ldg(base + t + TSIZE));
    }
}

// ---------------------------------------------------------------------------
// Kernel 2: hash-grid encode. One thread per point.
// Per level: 8 independent float2 gathers (good MLP), trilinear weights,
// immediate 8B store of the level's (f0,f1) pair.
// ---------------------------------------------------------------------------
__global__ void __launch_bounds__(256)
encode_kernel(const float* __restrict__ x,
              const float* __restrict__ resolution,
              float*       __restrict__ out,
              int n) {
    const int p = blockIdx.x * blockDim.x + threadIdx.x;
    if (p >= n) return;

    const float px = __ldg(x + 3 * (size_t)p + 0);
    const float py = __ldg(x + 3 * (size_t)p + 1);
    const float pz = __ldg(x + 3 * (size_t)p + 2);

    float2* outp = reinterpret_cast<float2*>(out + (size_t)p * (NLVL * 2));

    #pragma unroll 4
    for (int l = 0; l < NLVL; ++l) {
        const float res = __ldg(resolution + l);
        const float xs = px * res, ys = py * res, zs = pz * res;
        const float fx0 = floorf(xs), fy0 = floorf(ys), fz0 = floorf(zs);
        const float fx = xs - fx0, fy = ys - fy0, fz = zs - fz0;

        const unsigned ix = (unsigned)fx0;
        const unsigned iy = (unsigned)fy0;
        const unsigned iz = (unsigned)fz0;

        // per-dim hashes for corner bit 0/1 (prime for x is 1)
        const unsigned hx0 = ix,              hx1 = ix + 1u;
        const unsigned hy0 = iy * P2,         hy1 = (iy + 1u) * P2;
        const unsigned hz0 = iz * P3,         hz1 = (iz + 1u) * P3;

        const float wx0 = 1.0f - fx, wx1 = fx;
        const float wy0 = 1.0f - fy, wy1 = fy;
        const float wz0 = 1.0f - fz, wz1 = fz;

        const float2* tab = g_packed + ((size_t)l << LOG_T);

        float2 acc = make_float2(0.0f, 0.0f);
        #pragma unroll
        for (int c = 0; c < 8; ++c) {
            const unsigned h = ((c & 4) ? hx1 : hx0)
                             ^ ((c & 2) ? hy1 : hy0)
                             ^ ((c & 1) ? hz1 : hz0);
            const float w = ((c & 4) ? wx1 : wx0)
                          * ((c & 2) ? wy1 : wy0)
                          * ((c & 1) ? wz1 : wz0);
            const float2 f = __ldg(tab + (h & TMASK));
            acc.x = fmaf(w, f.x, acc.x);
            acc.y = fmaf(w, f.y, acc.y);
        }
        outp[l] = acc;
    }
}

// ---------------------------------------------------------------------------
// Launch wrapper. Inputs (metadata order): x [n,3] f32, hashmap [L,F,T] f32,
// resolution [L] f32. Output: [n, L*F] f32.
// ---------------------------------------------------------------------------
extern "C" void kernel_launch(void* const* d_in, const int* in_sizes, int n_in,
                              void* d_out, int out_size) {
    const float* x          = (const float*)d_in[0];
    const float* hashmap    = (const float*)d_in[1];
    const float* resolution = (const float*)d_in[2];
    float* out = (float*)d_out;

    const int n = in_sizes[0] / 3;

    // repack: 8.4M float2 elements
    const int total = NLVL * (int)TSIZE;
    const int rb = 256;
    const int rg = (total + rb - 1) / rb;
    repack_kernel<<<rg, rb>>>(hashmap);

    const int eb = 256;
    const int eg = (n + eb - 1) / eb;
    encode_kernel<<<eg, eb>>>(x, resolution, out, n);
}

// round 2
// speedup vs baseline: 1.1047x; 1.1047x over previous
#include <cuda_runtime.h>
#include <cstdint>

// Problem constants (match reference)
#define NLVL   16
#define LOG_T  19
#define TSIZE  (1u << LOG_T)          // 524288
#define TMASK  (TSIZE - 1u)
#define P2     2654435761u
#define P3     805459861u

#define L0RES  17                     // vertices per dim at level 0 (res 16)
#define L0N    (17 * 17 * 17)         // 4913 vertices

#define EBLK   512                    // encode block size (16 warps)

// 64 MB repacked table: [L, T] of float2 (feature-interleaved)
__device__ float2 g_packed[NLVL * TSIZE];
// Level-0 vertex table: value = table0[hash(v)] for every vertex v of the 17^3 grid
__device__ float2 g_lvl0[L0N];

// ---------------------------------------------------------------------------
// Kernel 1: repack hashmap [L, F, T] -> [L, T, {f0,f1}]
// ---------------------------------------------------------------------------
__global__ void repack_kernel(const float* __restrict__ hm) {
    const int total = NLVL * (int)TSIZE;
    for (int i = blockIdx.x * blockDim.x + threadIdx.x; i < total;
         i += gridDim.x * blockDim.x) {
        const int l = i >> LOG_T;
        const int t = i & (int)TMASK;
        const float* base = hm + (size_t)l * 2u * TSIZE;
        g_packed[i] = make_float2(__ldg(base + t), __ldg(base + t + TSIZE));
    }
}

// ---------------------------------------------------------------------------
// Kernel 1b: materialize level-0 vertex values (4913 gathers, once)
// ---------------------------------------------------------------------------
__global__ void lvl0_kernel(const float* __restrict__ hm) {
    const int v = blockIdx.x * blockDim.x + threadIdx.x;
    if (v >= L0N) return;
    const unsigned ix = v / (L0RES * L0RES);
    const unsigned iy = (v / L0RES) % L0RES;
    const unsigned iz = v % L0RES;
    const unsigned h = (ix ^ (iy * P2) ^ (iz * P3)) & TMASK;
    g_lvl0[v] = make_float2(__ldg(hm + h), __ldg(hm + TSIZE + h));
}

// ---------------------------------------------------------------------------
// Kernel 2: hash-grid encode.
//  - level 0 served from shared memory (17^3 vertex array)
//  - levels 1..15 via 8B float2 gathers from g_packed (L2-resident)
//  - output staged per warp in smem (stride-17 pad) and written coalesced
// ---------------------------------------------------------------------------
__global__ void __launch_bounds__(EBLK)
encode_kernel(const float* __restrict__ x,
              const float* __restrict__ resolution,
              float*       __restrict__ out,
              int n) {
    extern __shared__ float smem[];
    float2* s_l0 = reinterpret_cast<float2*>(smem);        // 4913 float2 (39304 B)
    // staging starts at float offset 9856 (39424 B, 16B aligned)
    float* s_stage = smem + 9856;                          // 16 warps x 544 floats

    const int tid  = threadIdx.x;
    const int warp = tid >> 5;
    const int lane = tid & 31;
    float* st = s_stage + warp * 544;                      // 32 rows x 17 floats

    // cooperative coalesced load of the level-0 vertex table
    for (int v = tid; v < L0N; v += EBLK) s_l0[v] = g_lvl0[v];
    __syncthreads();

    const int p = blockIdx.x * EBLK + tid;
    const bool valid = (p < n);
    float px = 0.0f, py = 0.0f, pz = 0.0f;
    if (valid) {
        px = __ldg(x + 3 * (size_t)p + 0);
        py = __ldg(x + 3 * (size_t)p + 1);
        pz = __ldg(x + 3 * (size_t)p + 2);
    }

    const int warp_base = blockIdx.x * EBLK + warp * 32;

    #pragma unroll
    for (int half = 0; half < 2; ++half) {
        #pragma unroll 2
        for (int li = 0; li < 8; ++li) {
            const int l = half * 8 + li;
            const float res = __ldg(resolution + l);
            const float xs = px * res, ys = py * res, zs = pz * res;
            const float fx0 = floorf(xs), fy0 = floorf(ys), fz0 = floorf(zs);
            const float fx = xs - fx0, fy = ys - fy0, fz = zs - fz0;

            const unsigned ix = (unsigned)fx0;
            const unsigned iy = (unsigned)fy0;
            const unsigned iz = (unsigned)fz0;

            const float wx0 = 1.0f - fx, wx1 = fx;
            const float wy0 = 1.0f - fy, wy1 = fy;
            const float wz0 = 1.0f - fz, wz1 = fz;

            float2 acc = make_float2(0.0f, 0.0f);

            if (l == 0) {
                // shared-memory path: direct vertex lookup, no hashing
                const int base = ((int)ix * L0RES + (int)iy) * L0RES + (int)iz;
                #pragma unroll
                for (int c = 0; c < 8; ++c) {
                    const int vid = base + ((c >> 2) & 1) * (L0RES * L0RES)
                                         + ((c >> 1) & 1) * L0RES
                                         + (c & 1);
                    const float w = ((c & 4) ? wx1 : wx0)
                                  * ((c & 2) ? wy1 : wy0)
                                  * ((c & 1) ? wz1 : wz0);
                    const float2 f = s_l0[vid];
                    acc.x = fmaf(w, f.x, acc.x);
                    acc.y = fmaf(w, f.y, acc.y);
                }
            } else {
                const unsigned hx0 = ix,       hx1 = ix + 1u;
                const unsigned hy0 = iy * P2,  hy1 = (iy + 1u) * P2;
                const unsigned hz0 = iz * P3,  hz1 = (iz + 1u) * P3;
                const float2* tab = g_packed + ((size_t)l << LOG_T);
                #pragma unroll
                for (int c = 0; c < 8; ++c) {
                    const unsigned h = ((c & 4) ? hx1 : hx0)
                                     ^ ((c & 2) ? hy1 : hy0)
                                     ^ ((c & 1) ? hz1 : hz0);
                    const float w = ((c & 4) ? wx1 : wx0)
                                  * ((c & 2) ? wy1 : wy0)
                                  * ((c & 1) ? wz1 : wz0);
                    const float2 f = __ldg(tab + (h & TMASK));
                    acc.x = fmaf(w, f.x, acc.x);
                    acc.y = fmaf(w, f.y, acc.y);
                }
            }

            // stage into padded smem row (conflict-free: 17*lane distinct mod 32)
            st[lane * 17 + 2 * li + 0] = acc.x;
            st[lane * 17 + 2 * li + 1] = acc.y;
        }
        __syncwarp();

        // coalesced flush: 16 iterations, 2 rows (2x64B) per iteration
        #pragma unroll
        for (int i = 0; i < 16; ++i) {
            const int r = 2 * i + (lane >> 4);
            const int c = lane & 15;
            const int prow = warp_base + r;
            if (prow < n)
                out[(size_t)prow * (NLVL * 2) + half * 16 + c] = st[r * 17 + c];
        }
        __syncwarp();
    }
}

// ---------------------------------------------------------------------------
// Launch wrapper. Inputs: x [n,3] f32, hashmap [L,F,T] f32, resolution [L] f32.
// ---------------------------------------------------------------------------
extern "C" void kernel_launch(void* const* d_in, const int* in_sizes, int n_in,
                              void* d_out, int out_size) {
    const float* x          = (const float*)d_in[0];
    const float* hashmap    = (const float*)d_in[1];
    const float* resolution = (const float*)d_in[2];
    float* out = (float*)d_out;

    const int n = in_sizes[0] / 3;

    // opt-in to >48KB dynamic smem (idempotent, not a stream op)
    static const int SMEM_BYTES = 9856 * 4 + 16 * 544 * 4;  // 39424 + 34816 = 74240
    cudaFuncSetAttribute(encode_kernel,
                         cudaFuncAttributeMaxDynamicSharedMemorySize, SMEM_BYTES);

    // repack: 8.4M float2 elements
    const int total = NLVL * (int)TSIZE;
    repack_kernel<<<(total + 255) / 256, 256>>>(hashmap);
    lvl0_kernel<<<(L0N + 255) / 256, 256>>>(hashmap);

    const int eg = (n + EBLK - 1) / EBLK;
    encode_kernel<<<eg, EBLK, SMEM_BYTES>>>(x, resolution, out, n);
}